// round 15
// baseline (speedup 1.0000x reference)
#include <cuda_runtime.h>
#include <cuda_bf16.h>
#include <stdint.h>

#define BB 64
#define TT 1024
#define DD 128
#define HH 512
#define ZZ 64
#define G4 2048
#define TB 65536
#define WPAD 520
#define SPAD 520
#define NSCAN 512
#define NCTA 128
#define FLSTR 32   // flag stride in u32 (128B line per flag)

// ---------------- static scratch ----------------
__device__ float          g_gx[(size_t)TB * G4];
__device__ __nv_bfloat16  g_hs[(size_t)TB * HH];
__device__ __nv_bfloat16  g_xth[(size_t)TB * DD];
__device__ __nv_bfloat16  g_xtl[(size_t)TB * DD];
__device__ __nv_bfloat16  g_wih0h[G4 * DD];
__device__ __nv_bfloat16  g_wih0l[G4 * DD];
__device__ __nv_bfloat16  g_opw[DD * HH];
__device__ float          g_bsum[4][G4];
// state buffers, FRAGMENT-MAJOR layout (R9)
__device__ uint32_t       g_e0[2][BB * 512];
__device__ uint32_t       g_e1[2][BB * 512];
__device__ uint32_t       g_d0[2][BB * 256];
__device__ uint32_t       g_d1[2][BB * 256];
__device__ float          g_M[BB * 2 * HH];
__device__ float          g_zbuf[BB * ZZ];
__device__ unsigned       g_flagsE[NCTA * FLSTR];
__device__ unsigned       g_flagsD[NCTA * FLSTR];

__device__ __forceinline__ float fsig(float x)  { return __fdividef(1.f, 1.f + __expf(-x)); }
__device__ __forceinline__ float ftanhx(float x){ return 1.f - __fdividef(2.f, __expf(2.f * x) + 1.f); }
__device__ __forceinline__ uint32_t pk2(__nv_bfloat16 a, __nv_bfloat16 b) {
    return ((uint32_t)*(unsigned short*)&b << 16) | *(unsigned short*)&a;
}
__device__ __forceinline__ float bfl(uint32_t w, int hi) {
    unsigned short us = hi ? (unsigned short)(w >> 16) : (unsigned short)(w & 0xffff);
    __nv_bfloat16 b = *reinterpret_cast<__nv_bfloat16*>(&us);
    return __bfloat162float(b);
}
__device__ __forceinline__ int fidx_enc(int row, int col2) {
    int wj = row >> 4, qrr = row & 15, fr = qrr >> 3, qr = qrr & 7;
    int kt = col2 >> 3, ch = (col2 >> 2) & 1, qc = col2 & 3;
    return (((wj * 32 + kt) * 4 + fr + 2 * ch) << 6) + ((qr * 4 + qc) << 1);
}
__device__ __forceinline__ int fidx_dec(int row, int col2) {
    int wj = row >> 4, qrr = row & 15, fr = qrr >> 3, qr = qrr & 7;
    int kt = col2 >> 3, ch = (col2 >> 2) & 1, qc = col2 & 3;
    return (((wj * 32 + kt) * 4 + fr + 2 * ch) << 5) + (qr * 4 + qc);
}

#define MMA_BF16(ACC, A0,A1,A2,A3, B0,B1) \
    asm volatile( \
        "mma.sync.aligned.m16n8k16.row.col.f32.bf16.bf16.f32 " \
        "{%0,%1,%2,%3}, {%4,%5,%6,%7}, {%8,%9}, {%0,%1,%2,%3};\n" \
        : "+f"(ACC[0]), "+f"(ACC[1]), "+f"(ACC[2]), "+f"(ACC[3]) \
        : "r"(A0), "r"(A1), "r"(A2), "r"(A3), "r"(B0), "r"(B1))

#define LDCG2(V, P) asm volatile("ld.global.cg.v2.u32 {%0,%1}, [%2];" \
    : "=r"(V.x), "=r"(V.y) : "l"(P))
#define LDCG1(V, P) asm volatile("ld.global.cg.u32 %0, [%1];" : "=r"(V) : "l"(P))
#define STCG2(P, A, B) asm volatile("st.global.cg.v2.u32 [%0], {%1,%2};" :: "l"(P), "r"(A), "r"(B))
#define STCG1(P, V) asm volatile("st.global.cg.u32 [%0], %1;" :: "l"(P), "r"(V))

#define LDFLAG(V, P) asm volatile("ld.relaxed.gpu.global.u32 %0, [%1];" : "=r"(V) : "l"(P) : "memory")
#define STFLAG(P, V) asm volatile("st.relaxed.gpu.global.u32 [%0], %1;" :: "l"(P), "r"(V) : "memory")
#define FENCE_GPU()  asm volatile("fence.acq_rel.gpu;" ::: "memory")

__device__ __forceinline__ void bar_pub(unsigned* flags, int bid, unsigned fl) {
    __syncthreads();
    if (threadIdx.x == 0) { FENCE_GPU(); STFLAG(flags + bid * FLSTR, fl); }
}
// champion barrier: warp0-only poll + trailing __syncthreads
__device__ __forceinline__ void bar_poll(unsigned* flags, unsigned fl, int warp, int lane) {
    if (warp == 0) {
        bool ok;
        do {
            unsigned t0, t1, t2, t3;
            LDFLAG(t0, flags + lane * FLSTR);
            LDFLAG(t1, flags + (lane + 32) * FLSTR);
            LDFLAG(t2, flags + (lane + 64) * FLSTR);
            LDFLAG(t3, flags + (lane + 96) * FLSTR);
            ok = (t0 >= fl) & (t1 >= fl) & (t2 >= fl) & (t3 >= fl);
        } while (!__all_sync(0xffffffffu, ok));
        FENCE_GPU();
    }
    __syncthreads();
}

// ---- encoder MMA core: fragment-major A loads ----
template<int NKT>
__device__ __forceinline__ void enc_mma_run(
    float acc[4][4], const uint32_t* __restrict__ hb, const uint32_t* __restrict__ Wp,
    int ktbase, int wj, int lane, int qc, int qr)
{
    uint2 A[2][2][4];
#define ENC_LOAD(buf, c) { \
    _Pragma("unroll") \
    for (int u2 = 0; u2 < 2; ++u2) { \
        const uint32_t* ab = hb + (((wj * 32 + ktbase + (c) * 2 + u2) * 4) << 6) + lane * 2; \
        LDCG2(A[buf][u2][0], ab); \
        LDCG2(A[buf][u2][1], ab + 64); \
        LDCG2(A[buf][u2][2], ab + 128); \
        LDCG2(A[buf][u2][3], ab + 192); } }
    ENC_LOAD(0, 0)
    #pragma unroll
    for (int c = 0; c < NKT / 2; ++c) {
        if (c + 1 < NKT / 2) ENC_LOAD((c + 1) & 1, c + 1)
        #pragma unroll
        for (int u = 0; u < 2; ++u) {
            int po = (ktbase + c * 2 + u) * 16 + qc * 2;
            uint2 a0 = A[c & 1][u][0], a1 = A[c & 1][u][1];
            uint2 a2 = A[c & 1][u][2], a3 = A[c & 1][u][3];
            #pragma unroll
            for (int i = 0; i < 4; ++i) {
                const uint32_t* wr = Wp + (i * 8 + qr) * WPAD;
                uint2 b0 = *(const uint2*)(wr + po);
                uint2 b1 = *(const uint2*)(wr + po + 8);
                MMA_BF16(acc[i], a0.x, a1.x, a2.x, a3.x, b0.x, b1.x);
                MMA_BF16(acc[i], a0.x, a1.x, a2.x, a3.x, b0.y, b1.y);
                MMA_BF16(acc[i], a0.y, a1.y, a2.y, a3.y, b0.x, b1.x);
            }
        }
    }
#undef ENC_LOAD
}

// ---- decoder MMA core ----
template<int NKT>
__device__ __forceinline__ void dec_mma_run(
    float acc[4][4], const uint32_t* __restrict__ hb, const __nv_bfloat16* __restrict__ Wp,
    int ktbase, int wj, int lane, int qc, int qr)
{
    uint32_t A[2][2][4];
#define DEC_LOAD(buf, c) { \
    _Pragma("unroll") \
    for (int u2 = 0; u2 < 2; ++u2) { \
        const uint32_t* ab = hb + (((wj * 32 + ktbase + (c) * 2 + u2) * 4) << 5) + lane; \
        LDCG1(A[buf][u2][0], ab); \
        LDCG1(A[buf][u2][1], ab + 32); \
        LDCG1(A[buf][u2][2], ab + 64); \
        LDCG1(A[buf][u2][3], ab + 96); } }
    DEC_LOAD(0, 0)
    #pragma unroll
    for (int c = 0; c < NKT / 2; ++c) {
        if (c + 1 < NKT / 2) DEC_LOAD((c + 1) & 1, c + 1)
        #pragma unroll
        for (int u = 0; u < 2; ++u) {
            int k0 = (ktbase + c * 2 + u) * 16 + qc * 2;
            uint32_t a0 = A[c & 1][u][0], a1 = A[c & 1][u][1];
            uint32_t a2 = A[c & 1][u][2], a3 = A[c & 1][u][3];
            #pragma unroll
            for (int i = 0; i < 4; ++i) {
                const __nv_bfloat16* wr = Wp + (i * 8 + qr) * SPAD;
                uint32_t b0 = *(const uint32_t*)(wr + k0);
                uint32_t b1 = *(const uint32_t*)(wr + k0 + 8);
                MMA_BF16(acc[i], a0, a1, a2, a3, b0, b1);
            }
        }
    }
#undef DEC_LOAD
}

// ================= fused encoder scan =================
__global__ void __launch_bounds__(NSCAN, 1) enc_scan(
    const float* __restrict__ Whh0, const float* __restrict__ Wih1,
    const float* __restrict__ Whh1, const float* __restrict__ gx)
{
    extern __shared__ uint32_t smu[];
    float4* Sred = (float4*)(smu + 64 * WPAD);   // 4 slabs x 128 pos x 4 gates
    const int tid = threadIdx.x, bid = blockIdx.x;
    const int layerid = bid >> 6, ci = bid & 63, j0 = ci * 8;
    const int warp = tid >> 5, lane = tid & 31;
    const int grp = warp >> 2, wj = warp & 3;
    const int qr = lane >> 2, qc = lane & 3;
    const int r0 = wj * 16 + qr;
    const int wroff = (((wj * 32 + (ci >> 1)) * 4 + (ci & 1) * 2) << 6) + lane * 2;
    const int th = wj * 32 + lane;

    if (layerid == 0) {
        for (int idx = tid; idx < 32 * 256; idx += NSCAN) {
            int rl = idx >> 8, p = idx & 255;
            int grow = (rl >> 3) * 512 + j0 + (rl & 7);
            float2 v = *(const float2*)(Whh0 + (size_t)grow * 512 + 2 * p);
            __nv_bfloat16 h0 = __float2bfloat16_rn(v.x), h1v = __float2bfloat16_rn(v.y);
            __nv_bfloat16 l0 = __float2bfloat16_rn(v.x - __bfloat162float(h0));
            __nv_bfloat16 l1 = __float2bfloat16_rn(v.y - __bfloat162float(h1v));
            smu[rl * WPAD + 2 * p]     = pk2(h0, h1v);
            smu[rl * WPAD + 2 * p + 1] = pk2(l0, l1);
        }
        for (int idx = tid; idx < 512; idx += NSCAN)
            STCG1(&g_e0[1][ci * 512 + idx], 0u);
    } else {
        for (int idx = tid; idx < 2 * 32 * 256; idx += NSCAN) {
            int w = idx >= 32 * 256;
            int ii = idx - w * 32 * 256;
            int rl = ii >> 8, p = ii & 255;
            int grow = (rl >> 3) * 512 + j0 + (rl & 7);
            const float* W = w ? Whh1 : Wih1;
            float2 v = *(const float2*)(W + (size_t)grow * 512 + 2 * p);
            __nv_bfloat16 h0 = __float2bfloat16_rn(v.x), h1v = __float2bfloat16_rn(v.y);
            __nv_bfloat16 l0 = __float2bfloat16_rn(v.x - __bfloat162float(h0));
            __nv_bfloat16 l1 = __float2bfloat16_rn(v.y - __bfloat162float(h1v));
            uint32_t* dst = smu + w * 32 * WPAD + rl * WPAD;
            dst[2 * p]     = pk2(h0, h1v);
            dst[2 * p + 1] = pk2(l0, l1);
        }
        for (int idx = tid; idx < 512; idx += NSCAN)
            STCG1(&g_e1[1][ci * 512 + idx], 0u);
    }

    float pf[4][4];
    if (layerid == 1 && grp == 0) {
        #pragma unroll
        for (int i = 0; i < 4; ++i) {
            int col = i * 512 + j0 + qc * 2;
            float b0 = g_bsum[1][col], b1 = g_bsum[1][col + 1];
            pf[i][0] = b0; pf[i][1] = b1; pf[i][2] = b0; pf[i][3] = b1;
        }
    }
    unsigned fl = 1;
    bar_pub(g_flagsE, bid, fl);
    if (layerid == 0 && grp == 0) {
        #pragma unroll
        for (int i = 0; i < 4; ++i) {
            int col = i * 512 + j0 + qc * 2;
            float2 lo = *(const float2*)(gx + (size_t)r0       * 2048 + col);
            float2 hi = *(const float2*)(gx + (size_t)(r0 + 8) * 2048 + col);
            pf[i][0] = lo.x; pf[i][1] = lo.y; pf[i][2] = hi.x; pf[i][3] = hi.y;
        }
    }
    bar_poll(g_flagsE, fl, warp, lane); fl++;

    float creg2[2] = {0.f, 0.f};   // grp0: k0,k1 ; grp1: k2,k3
    for (int r = 0; r <= TT; ++r) {
        const bool active = (layerid == 0) ? (r < TT) : (r >= 1);
        float acc[4][4];
        if (active) {
            #pragma unroll
            for (int i = 0; i < 4; ++i)
                #pragma unroll
                for (int k = 0; k < 4; ++k) acc[i][k] = (grp == 0) ? pf[i][k] : 0.f;

            if (layerid == 0) {
                enc_mma_run<8>(acc, g_e0[(r - 1) & 1], smu, grp * 8, wj, lane, qc, qr);
            } else {
                const uint32_t* hb = (grp < 2) ? g_e1[r & 1] : g_e0[(r - 1) & 1];
                const uint32_t* Wp = (grp < 2) ? (smu + 32 * WPAD) : smu;
                enc_mma_run<16>(acc, hb, Wp, (grp & 1) * 16, wj, lane, qc, qr);
            }
            int base = grp * 512 + th * 4;
            #pragma unroll
            for (int i = 0; i < 4; ++i)
                Sred[base + i] = make_float4(acc[i][0], acc[i][1], acc[i][2], acc[i][3]);
        }
        __syncthreads();
        if (active && grp < 2) {
            // canonical ((g0+g1)+g2)+g3 — g0 slab already contains pf
            #pragma unroll
            for (int i = 0; i < 4; ++i) {
                float4 s0 = Sred[0 * 512 + th * 4 + i];
                float4 s1 = Sred[1 * 512 + th * 4 + i];
                float4 s2 = Sred[2 * 512 + th * 4 + i];
                float4 s3 = Sred[3 * 512 + th * 4 + i];
                acc[i][0] = ((s0.x + s1.x) + s2.x) + s3.x;
                acc[i][1] = ((s0.y + s1.y) + s2.y) + s3.y;
                acc[i][2] = ((s0.z + s1.z) + s2.z) + s3.z;
                acc[i][3] = ((s0.w + s1.w) + s2.w) + s3.w;
            }
            float hv[2];
            #pragma unroll
            for (int j = 0; j < 2; ++j) {
                int k = grp * 2 + j;
                float ig = fsig(acc[0][k]);
                float fg = fsig(acc[1][k]);
                float gg = ftanhx(acc[2][k]);
                float og = fsig(acc[3][k]);
                creg2[j] = fg * creg2[j] + ig * gg;
                hv[j]    = og * ftanhx(creg2[j]);
            }
            __nv_bfloat16 ha = __float2bfloat16_rn(hv[0]);
            __nv_bfloat16 hb2 = __float2bfloat16_rn(hv[1]);
            __nv_bfloat16 la = __float2bfloat16_rn(hv[0] - __bfloat162float(ha));
            __nv_bfloat16 lb = __float2bfloat16_rn(hv[1] - __bfloat162float(hb2));
            uint32_t* wb = (layerid == 0) ? g_e0[r & 1] : g_e1[(r - 1) & 1];
            STCG2(wb + wroff + grp * 64, pk2(ha, hb2), pk2(la, lb));
        }
        if (r < TT) {
            bar_pub(g_flagsE, bid, fl);
            if (layerid == 0 && grp == 0 && r + 1 < TT) {
                #pragma unroll
                for (int i = 0; i < 4; ++i) {
                    int col = i * 512 + j0 + qc * 2;
                    float2 lo = *(const float2*)(gx + (size_t)((r + 1) * 64 + r0)     * 2048 + col);
                    float2 hi = *(const float2*)(gx + (size_t)((r + 1) * 64 + r0 + 8) * 2048 + col);
                    pf[i][0] = lo.x; pf[i][1] = lo.y; pf[i][2] = hi.x; pf[i][3] = hi.y;
                }
            }
            bar_poll(g_flagsE, fl, warp, lane); fl++;
        }
    }
}

// ================= fused decoder scan =================
__global__ void __launch_bounds__(NSCAN, 1) dec_scan(
    const float* __restrict__ Whh0, const float* __restrict__ Wih1,
    const float* __restrict__ Whh1)
{
    extern __shared__ uint32_t smu[];
    __nv_bfloat16* Wsm = (__nv_bfloat16*)smu;
    float4* Sred = (float4*)(smu + 64 * (SPAD / 2));
    const int tid = threadIdx.x, bid = blockIdx.x;
    const int layerid = bid >> 6, ci = bid & 63, j0 = ci * 8;
    const int warp = tid >> 5, lane = tid & 31;
    const int grp = warp >> 2, wj = warp & 3;
    const int qr = lane >> 2, qc = lane & 3;
    const int r0 = wj * 16 + qr;
    const int wroff = (((wj * 32 + (ci >> 1)) * 4 + (ci & 1) * 2) << 5) + lane;
    const int th = wj * 32 + lane;

    if (layerid == 0) {
        for (int idx = tid; idx < 32 * 256; idx += NSCAN) {
            int rl = idx >> 8, p = idx & 255;
            int grow = (rl >> 3) * 512 + j0 + (rl & 7);
            float2 v = *(const float2*)(Whh0 + (size_t)grow * 512 + 2 * p);
            ((uint32_t*)Wsm)[rl * (SPAD / 2) + p] =
                pk2(__float2bfloat16(v.x), __float2bfloat16(v.y));
        }
        for (int idx = tid; idx < 64 * 4; idx += NSCAN) {
            int row = idx >> 2, pp = idx & 3;
            float2 v = *(const float2*)(g_M + row * 512 + j0 + 2 * pp);
            STCG1(&g_d0[1][fidx_dec(row, 4 * ci + pp)],
                  pk2(__float2bfloat16(v.x), __float2bfloat16(v.y)));
        }
    } else {
        for (int idx = tid; idx < 2 * 32 * 256; idx += NSCAN) {
            int w = idx >= 32 * 256;
            int ii = idx - w * 32 * 256;
            int rl = ii >> 8, p = ii & 255;
            int grow = (rl >> 3) * 512 + j0 + (rl & 7);
            const float* W = w ? Wih1 : Whh1;
            float2 v = *(const float2*)(W + (size_t)grow * 512 + 2 * p);
            ((uint32_t*)Wsm)[w * 32 * (SPAD / 2) + rl * (SPAD / 2) + p] =
                pk2(__float2bfloat16(v.x), __float2bfloat16(v.y));
        }
        for (int idx = tid; idx < 64 * 4; idx += NSCAN) {
            int row = idx >> 2, pp = idx & 3;
            float2 v = *(const float2*)(g_M + 32768 + row * 512 + j0 + 2 * pp);
            STCG1(&g_d1[1][fidx_dec(row, 4 * ci + pp)],
                  pk2(__float2bfloat16(v.x), __float2bfloat16(v.y)));
        }
    }

    float pf[4][4];
    if (grp == 0) {
        const float* bs = g_bsum[layerid == 0 ? 2 : 3];
        #pragma unroll
        for (int i = 0; i < 4; ++i) {
            int col = i * 512 + j0 + qc * 2;
            float b0 = bs[col], b1 = bs[col + 1];
            pf[i][0] = b0; pf[i][1] = b1; pf[i][2] = b0; pf[i][3] = b1;
        }
    }
    unsigned fl = 1;
    bar_pub(g_flagsD, bid, fl);
    bar_poll(g_flagsD, fl, warp, lane); fl++;

    float creg2[2] = {0.f, 0.f};
    for (int r = 0; r <= TT; ++r) {
        const bool active = (layerid == 0) ? (r < TT) : (r >= 1);
        float acc[4][4];
        uint32_t qv = 0;
        if (active) {
            #pragma unroll
            for (int i = 0; i < 4; ++i)
                #pragma unroll
                for (int k = 0; k < 4; ++k) acc[i][k] = (grp == 0) ? pf[i][k] : 0.f;

            if (layerid == 0) {
                dec_mma_run<8>(acc, g_d0[(r - 1) & 1], Wsm, grp * 8, wj, lane, qc, qr);
            } else {
                const uint32_t* hb = (grp < 2) ? g_d1[r & 1] : g_d0[(r - 1) & 1];
                const __nv_bfloat16* Wp = (grp < 2) ? Wsm : Wsm + 32 * SPAD;
                dec_mma_run<16>(acc, hb, Wp, (grp & 1) * 16, wj, lane, qc, qr);
            }
            int base = grp * 512 + th * 4;
            #pragma unroll
            for (int i = 0; i < 4; ++i)
                Sred[base + i] = make_float4(acc[i][0], acc[i][1], acc[i][2], acc[i][3]);
        }
        __syncthreads();
        if (active && grp < 2) {
            #pragma unroll
            for (int i = 0; i < 4; ++i) {
                float4 s0 = Sred[0 * 512 + th * 4 + i];
                float4 s1 = Sred[1 * 512 + th * 4 + i];
                float4 s2 = Sred[2 * 512 + th * 4 + i];
                float4 s3 = Sred[3 * 512 + th * 4 + i];
                acc[i][0] = ((s0.x + s1.x) + s2.x) + s3.x;
                acc[i][1] = ((s0.y + s1.y) + s2.y) + s3.y;
                acc[i][2] = ((s0.z + s1.z) + s2.z) + s3.z;
                acc[i][3] = ((s0.w + s1.w) + s2.w) + s3.w;
            }
            float hv[2];
            #pragma unroll
            for (int j = 0; j < 2; ++j) {
                int k = grp * 2 + j;
                float ig = fsig(acc[0][k]);
                float fg = fsig(acc[1][k]);
                float gg = ftanhx(acc[2][k]);
                float og = fsig(acc[3][k]);
                creg2[j] = fg * creg2[j] + ig * gg;
                hv[j]    = og * ftanhx(creg2[j]);
            }
            qv = pk2(__float2bfloat16_rn(hv[0]), __float2bfloat16_rn(hv[1]));
            uint32_t* wb = (layerid == 0) ? g_d0[r & 1] : g_d1[(r - 1) & 1];
            STCG1(wb + wroff + grp * 32, qv);
        }
        if (r < TT) {
            bar_pub(g_flagsD, bid, fl);
            if (layerid == 1 && grp < 2 && r >= 1) {
                int t = r - 1, cb = j0 + qc * 2;
                *(uint32_t*)(g_hs + (size_t)(t * 64 + r0 + grp * 8) * 512 + cb) = qv;
            }
            bar_poll(g_flagsD, fl, warp, lane); fl++;
        } else if (layerid == 1 && grp < 2) {
            int t = TT - 1, cb = j0 + qc * 2;
            *(uint32_t*)(g_hs + (size_t)(t * 64 + r0 + grp * 8) * 512 + cb) = qv;
        }
    }
}

// ================= split-bf16 GEMM 128x128 =================
__global__ void __launch_bounds__(256, 2) gemm_split_kernel(
    const __nv_bfloat16* __restrict__ Ah, const __nv_bfloat16* __restrict__ Al,
    const __nv_bfloat16* __restrict__ Bh, const __nv_bfloat16* __restrict__ Bl,
    const float* __restrict__ bias, float* __restrict__ Cout, int N, int K)
{
    __shared__ __nv_bfloat16 Ash[128 * 40];
    __shared__ __nv_bfloat16 Asl[128 * 40];
    __shared__ __nv_bfloat16 Bsh[128 * 40];
    __shared__ __nv_bfloat16 Bsl[128 * 40];
    const int tid  = threadIdx.x;
    const int warp = tid >> 5, lane = tid & 31;
    const int qr   = lane >> 2, qc = lane & 3;
    const int wm   = warp >> 2, wn = warp & 3;
    const int m0   = blockIdx.x * 128;
    const int n0   = blockIdx.y * 128;

    float acc[4][4][4];
    #pragma unroll
    for (int a = 0; a < 4; ++a)
        #pragma unroll
        for (int b = 0; b < 4; ++b)
            #pragma unroll
            for (int c = 0; c < 4; ++c) acc[a][b][c] = 0.f;

    for (int kt = 0; kt < K; kt += 32) {
        #pragma unroll
        for (int u = 0; u < 2; ++u) {
            int idx = tid + u * 256;
            int r = idx >> 2, c8 = (idx & 3) << 3;
            *(uint4*)(Ash + r * 40 + c8) = *(const uint4*)(Ah + (size_t)(m0 + r) * K + kt + c8);
            *(uint4*)(Asl + r * 40 + c8) = *(const uint4*)(Al + (size_t)(m0 + r) * K + kt + c8);
            *(uint4*)(Bsh + r * 40 + c8) = *(const uint4*)(Bh + (size_t)(n0 + r) * K + kt + c8);
            *(uint4*)(Bsl + r * 40 + c8) = *(const uint4*)(Bl + (size_t)(n0 + r) * K + kt + c8);
        }
        __syncthreads();
        #pragma unroll
        for (int kk = 0; kk < 2; ++kk) {
            const int k0 = kk * 16 + qc * 2;
            #pragma unroll
            for (int mi = 0; mi < 4; ++mi) {
                int ar = wm * 64 + mi * 16 + qr;
                uint32_t ah0 = *(const uint32_t*)(Ash + ar * 40 + k0);
                uint32_t ah1 = *(const uint32_t*)(Ash + (ar + 8) * 40 + k0);
                uint32_t ah2 = *(const uint32_t*)(Ash + ar * 40 + k0 + 8);
                uint32_t ah3 = *(const uint32_t*)(Ash + (ar + 8) * 40 + k0 + 8);
                uint32_t al0 = *(const uint32_t*)(Asl + ar * 40 + k0);
                uint32_t al1 = *(const uint32_t*)(Asl + (ar + 8) * 40 + k0);
                uint32_t al2 = *(const uint32_t*)(Asl + ar * 40 + k0 + 8);
                uint32_t al3 = *(const uint32_t*)(Asl + (ar + 8) * 40 + k0 + 8);
                #pragma unroll
                for (int ni = 0; ni < 4; ++ni) {
                    int br = wn * 32 + ni * 8 + qr;
                    uint32_t bh0 = *(const uint32_t*)(Bsh + br * 40 + k0);
                    uint32_t bh1 = *(const uint32_t*)(Bsh + br * 40 + k0 + 8);
                    uint32_t bl0 = *(const uint32_t*)(Bsl + br * 40 + k0);
                    uint32_t bl1 = *(const uint32_t*)(Bsl + br * 40 + k0 + 8);
                    MMA_BF16(acc[mi][ni], ah0, ah1, ah2, ah3, bh0, bh1);
                    MMA_BF16(acc[mi][ni], ah0, ah1, ah2, ah3, bl0, bl1);
                    MMA_BF16(acc[mi][ni], al0, al1, al2, al3, bh0, bh1);
                }
            }
        }
        __syncthreads();
    }
    #pragma unroll
    for (int mi = 0; mi < 4; ++mi)
        #pragma unroll
        for (int ni = 0; ni < 4; ++ni) {
            int gn = n0 + wn * 32 + ni * 8 + qc * 2;
            float bv0 = bias[gn], bv1 = bias[gn + 1];
            #pragma unroll
            for (int h = 0; h < 2; ++h) {
                int gm = m0 + wm * 64 + mi * 16 + qr + h * 8;
                *(float2*)(Cout + (size_t)gm * N + gn) =
                    make_float2(acc[mi][ni][h * 2 + 0] + bv0, acc[mi][ni][h * 2 + 1] + bv1);
            }
        }
}

// ================= plain bf16 GEMM (output projection) =================
__global__ void __launch_bounds__(256, 2) gemm_bf16_kernel(
    const __nv_bfloat16* __restrict__ A, const __nv_bfloat16* __restrict__ Bw,
    const float* __restrict__ bias, float* __restrict__ Cout, int N, int K, int mode)
{
    __shared__ __nv_bfloat16 As[128 * 40];
    __shared__ __nv_bfloat16 Bs[128 * 40];
    const int tid  = threadIdx.x;
    const int warp = tid >> 5, lane = tid & 31;
    const int qr   = lane >> 2, qc = lane & 3;
    const int wm   = warp >> 2, wn = warp & 3;
    const int m0   = blockIdx.x * 128;
    const int n0   = blockIdx.y * 128;

    float acc[4][4][4];
    #pragma unroll
    for (int a = 0; a < 4; ++a)
        #pragma unroll
        for (int b = 0; b < 4; ++b)
            #pragma unroll
            for (int c = 0; c < 4; ++c) acc[a][b][c] = 0.f;

    for (int kt = 0; kt < K; kt += 32) {
        #pragma unroll
        for (int u = 0; u < 2; ++u) {
            int idx = tid + u * 256;
            int r = idx >> 2, c8 = (idx & 3) << 3;
            *(uint4*)(As + r * 40 + c8) = *(const uint4*)(A + (size_t)(m0 + r) * K + kt + c8);
            *(uint4*)(Bs + r * 40 + c8) = *(const uint4*)(Bw + (size_t)(n0 + r) * K + kt + c8);
        }
        __syncthreads();
        #pragma unroll
        for (int kk = 0; kk < 2; ++kk) {
            const int k0 = kk * 16 + qc * 2;
            #pragma unroll
            for (int mi = 0; mi < 4; ++mi) {
                int ar = wm * 64 + mi * 16 + qr;
                uint32_t a0 = *(const uint32_t*)(As + ar * 40 + k0);
                uint32_t a1 = *(const uint32_t*)(As + (ar + 8) * 40 + k0);
                uint32_t a2 = *(const uint32_t*)(As + ar * 40 + k0 + 8);
                uint32_t a3 = *(const uint32_t*)(As + (ar + 8) * 40 + k0 + 8);
                #pragma unroll
                for (int ni = 0; ni < 4; ++ni) {
                    int br = wn * 32 + ni * 8 + qr;
                    uint32_t b0 = *(const uint32_t*)(Bs + br * 40 + k0);
                    uint32_t b1 = *(const uint32_t*)(Bs + br * 40 + k0 + 8);
                    MMA_BF16(acc[mi][ni], a0, a1, a2, a3, b0, b1);
                }
            }
        }
        __syncthreads();
    }
    #pragma unroll
    for (int mi = 0; mi < 4; ++mi)
        #pragma unroll
        for (int ni = 0; ni < 4; ++ni) {
            int gn = n0 + wn * 32 + ni * 8 + qc * 2;
            float bv0 = bias[gn], bv1 = bias[gn + 1];
            #pragma unroll
            for (int h = 0; h < 2; ++h) {
                int gm = m0 + wm * 64 + mi * 16 + qr + h * 8;
                float v0 = acc[mi][ni][h * 2 + 0] + bv0;
                float v1 = acc[mi][ni][h * 2 + 1] + bv1;
                if (mode == 1) {
                    int tt = gm >> 6, bb = gm & 63;
                    *(float2*)(Cout + ((size_t)bb * TT + tt) * DD + gn) =
                        make_float2(fsig(v0), fsig(v1));
                } else {
                    *(float2*)(Cout + (size_t)gm * N + gn) = make_float2(v0, v1);
                }
            }
        }
}

// ================= prep / latent kernels =================
__global__ void prep_bias_kernel(
    const float* __restrict__ b0a, const float* __restrict__ b0b,
    const float* __restrict__ b1a, const float* __restrict__ b1b,
    const float* __restrict__ b2a, const float* __restrict__ b2b,
    const float* __restrict__ b3a, const float* __restrict__ b3b)
{
    int i = blockIdx.x * blockDim.x + threadIdx.x;
    if (i < 4 * G4) {
        int l = i >> 11, j = i & (G4 - 1);
        const float* pa = (l == 0) ? b0a : (l == 1) ? b1a : (l == 2) ? b2a : b3a;
        const float* pb = (l == 0) ? b0b : (l == 1) ? b1b : (l == 2) ? b2b : b3b;
        g_bsum[l][j] = pa[j] + pb[j];
    }
    if (i < NCTA) g_flagsE[i * FLSTR] = 0u;
}
__global__ void prep_xw_kernel(const float* __restrict__ x, const float* __restrict__ W) {
    int i = blockIdx.x * blockDim.x + threadIdx.x;
    if (i < TB * DD) {
        int d = i & (DD - 1);
        int r = i >> 7;
        int b = r & 63, t = r >> 6;
        float v = x[((size_t)b * TT + t) * DD + d];
        __nv_bfloat16 h = __float2bfloat16_rn(v);
        g_xth[i] = h;
        g_xtl[i] = __float2bfloat16_rn(v - __bfloat162float(h));
    }
    if (i < G4 * DD) {
        float v = W[i];
        __nv_bfloat16 h = __float2bfloat16_rn(v);
        g_wih0h[i] = h;
        g_wih0l[i] = __float2bfloat16_rn(v - __bfloat162float(h));
    }
}
__global__ void prep_opw_kernel(const float* __restrict__ W) {
    int i = blockIdx.x * blockDim.x + threadIdx.x;
    if (i < DD * HH) g_opw[i] = __float2bfloat16(W[i]);
}
__global__ void z_kernel(const float* __restrict__ tlW, const float* __restrict__ tlb,
                         float* __restrict__ zout) {
    int idx = blockIdx.x * blockDim.x + threadIdx.x;
    if (idx < BB * ZZ) {
        int b = idx >> 6, j = idx & 63;
        float s = 0.f;
        for (int p = 0; p < 256; ++p) {
            int off = fidx_enc(b, p);
            uint32_t wh = g_e1[1][off], wl = g_e1[1][off + 1];
            float h0 = bfl(wh, 0) + bfl(wl, 0);
            float h1 = bfl(wh, 1) + bfl(wl, 1);
            s += h0 * tlW[j * 512 + 2 * p] + h1 * tlW[j * 512 + 2 * p + 1];
        }
        s += tlb[j];
        g_zbuf[idx] = s;
        zout[idx] = s;
    }
}
__global__ void m_kernel(const float* __restrict__ lhW, const float* __restrict__ lhb) {
    int b = blockIdx.x, k1 = threadIdx.x;
    float s = 0.f;
    for (int j = 0; j < 64; ++j)
        s += g_zbuf[b * 64 + j] * lhW[k1 * 64 + j];
    g_M[b * 1024 + k1] = tanhf(s + lhb[k1]);
    if (b == 0 && k1 < NCTA) g_flagsD[k1 * FLSTR] = 0u;
}

extern "C" void kernel_launch(void* const* d_in, const int* in_sizes, int n_in,
                              void* d_out, int out_size) {
    const float* x     = (const float*)d_in[0];
    const float* eWih0 = (const float*)d_in[1];
    const float* eWhh0 = (const float*)d_in[2];
    const float* ebih0 = (const float*)d_in[3];
    const float* ebhh0 = (const float*)d_in[4];
    const float* eWih1 = (const float*)d_in[5];
    const float* eWhh1 = (const float*)d_in[6];
    const float* ebih1 = (const float*)d_in[7];
    const float* ebhh1 = (const float*)d_in[8];
    const float* dWhh0 = (const float*)d_in[10];
    const float* dbih0 = (const float*)d_in[11];
    const float* dbhh0 = (const float*)d_in[12];
    const float* dWih1 = (const float*)d_in[13];
    const float* dWhh1 = (const float*)d_in[14];
    const float* dbih1 = (const float*)d_in[15];
    const float* dbhh1 = (const float*)d_in[16];
    const float* tlW   = (const float*)d_in[17];
    const float* tlb   = (const float*)d_in[18];
    const float* lhW   = (const float*)d_in[19];
    const float* lhb   = (const float*)d_in[20];
    const float* opW   = (const float*)d_in[21];
    const float* opb   = (const float*)d_in[22];
    float* out = (float*)d_out;

    __nv_bfloat16 *p_xth, *p_xtl, *p_w0h, *p_w0l, *p_opw, *p_hs;
    float *p_gx, *p_bs;
    cudaGetSymbolAddress((void**)&p_xth, g_xth);
    cudaGetSymbolAddress((void**)&p_xtl, g_xtl);
    cudaGetSymbolAddress((void**)&p_gx, g_gx);
    cudaGetSymbolAddress((void**)&p_hs, g_hs);
    cudaGetSymbolAddress((void**)&p_bs, g_bsum);
    cudaGetSymbolAddress((void**)&p_w0h, g_wih0h);
    cudaGetSymbolAddress((void**)&p_w0l, g_wih0l);
    cudaGetSymbolAddress((void**)&p_opw, g_opw);

    const int ENC_SMEM = 64 * WPAD * 4 + 4 * 512 * 16;       // 165,888
    const int DEC_SMEM = 64 * (SPAD / 2) * 4 + 4 * 512 * 16; //  99,328
    cudaFuncSetAttribute(enc_scan, cudaFuncAttributeMaxDynamicSharedMemorySize, ENC_SMEM);
    cudaFuncSetAttribute(dec_scan, cudaFuncAttributeMaxDynamicSharedMemorySize, DEC_SMEM);

    prep_bias_kernel<<<32, 256>>>(ebih0, ebhh0, ebih1, ebhh1, dbih0, dbhh0, dbih1, dbhh1);
    prep_xw_kernel<<<TB * DD / 256, 256>>>(x, eWih0);
    dim3 gemm_grid(TB / 128, G4 / 128);
    gemm_split_kernel<<<gemm_grid, 256>>>(p_xth, p_xtl, p_w0h, p_w0l, p_bs + 0 * G4, p_gx, G4, DD);
    enc_scan<<<NCTA, NSCAN, ENC_SMEM>>>(eWhh0, eWih1, eWhh1, p_gx);
    z_kernel<<<(BB * ZZ + 255) / 256, 256>>>(tlW, tlb, out + (size_t)BB * TT * DD);
    m_kernel<<<BB, 1024>>>(lhW, lhb);
    dec_scan<<<NCTA, NSCAN, DEC_SMEM>>>(dWhh0, dWih1, dWhh1);
    prep_opw_kernel<<<DD * HH / 256, 256>>>(opW);
    dim3 op_grid(TB / 128, 1);
    gemm_bf16_kernel<<<op_grid, 256>>>(p_hs, p_opw, opb, out, DD, HH, 1);
}

// round 16
// speedup vs baseline: 1.1919x; 1.1919x over previous
#include <cuda_runtime.h>
#include <cuda_bf16.h>
#include <stdint.h>

#define BB 64
#define TT 1024
#define DD 128
#define HH 512
#define ZZ 64
#define G4 2048
#define TB 65536
#define WPAD 520
#define SPAD 520
#define NSCAN 512
#define NCTA 128
#define FLSTR 32   // flag stride in u32 (128B line per flag)

// ---------------- static scratch ----------------
__device__ float          g_gx[(size_t)TB * G4];
__device__ __nv_bfloat16  g_hs[(size_t)TB * HH];
__device__ __nv_bfloat16  g_xth[(size_t)TB * DD];
__device__ __nv_bfloat16  g_xtl[(size_t)TB * DD];
__device__ __nv_bfloat16  g_wih0h[G4 * DD];
__device__ __nv_bfloat16  g_wih0l[G4 * DD];
__device__ __nv_bfloat16  g_opw[DD * HH];
__device__ float          g_bsum[4][G4];
// state buffers, FRAGMENT-MAJOR layout (see R9)
__device__ uint32_t       g_e0[2][BB * 512];
__device__ uint32_t       g_e1[2][BB * 512];
__device__ uint32_t       g_d0[2][BB * 256];
__device__ uint32_t       g_d1[2][BB * 256];
__device__ float          g_M[BB * 2 * HH];
__device__ float          g_zbuf[BB * ZZ];
__device__ unsigned       g_flagsE[NCTA * FLSTR];   // one 128B line per flag
__device__ unsigned       g_flagsD[NCTA * FLSTR];

__device__ __forceinline__ float fsig(float x)  { return __fdividef(1.f, 1.f + __expf(-x)); }
__device__ __forceinline__ float ftanhx(float x){ return 1.f - __fdividef(2.f, __expf(2.f * x) + 1.f); }
__device__ __forceinline__ uint32_t pk2(__nv_bfloat16 a, __nv_bfloat16 b) {
    return ((uint32_t)*(unsigned short*)&b << 16) | *(unsigned short*)&a;
}
__device__ __forceinline__ float bfl(uint32_t w, int hi) {
    unsigned short us = hi ? (unsigned short)(w >> 16) : (unsigned short)(w & 0xffff);
    __nv_bfloat16 b = *reinterpret_cast<__nv_bfloat16*>(&us);
    return __bfloat162float(b);
}
__device__ __forceinline__ int fidx_enc(int row, int col2) {
    int wj = row >> 4, qrr = row & 15, fr = qrr >> 3, qr = qrr & 7;
    int kt = col2 >> 3, ch = (col2 >> 2) & 1, qc = col2 & 3;
    return (((wj * 32 + kt) * 4 + fr + 2 * ch) << 6) + ((qr * 4 + qc) << 1);
}
__device__ __forceinline__ int fidx_dec(int row, int col2) {
    int wj = row >> 4, qrr = row & 15, fr = qrr >> 3, qr = qrr & 7;
    int kt = col2 >> 3, ch = (col2 >> 2) & 1, qc = col2 & 3;
    return (((wj * 32 + kt) * 4 + fr + 2 * ch) << 5) + (qr * 4 + qc);
}

#define MMA_BF16(ACC, A0,A1,A2,A3, B0,B1) \
    asm volatile( \
        "mma.sync.aligned.m16n8k16.row.col.f32.bf16.bf16.f32 " \
        "{%0,%1,%2,%3}, {%4,%5,%6,%7}, {%8,%9}, {%0,%1,%2,%3};\n" \
        : "+f"(ACC[0]), "+f"(ACC[1]), "+f"(ACC[2]), "+f"(ACC[3]) \
        : "r"(A0), "r"(A1), "r"(A2), "r"(A3), "r"(B0), "r"(B1))

#define LDCG2(V, P) asm volatile("ld.global.cg.v2.u32 {%0,%1}, [%2];" \
    : "=r"(V.x), "=r"(V.y) : "l"(P))
#define LDCG1(V, P) asm volatile("ld.global.cg.u32 %0, [%1];" : "=r"(V) : "l"(P))
#define STCG2(P, A, B) asm volatile("st.global.cg.v2.u32 [%0], {%1,%2};" :: "l"(P), "r"(A), "r"(B))
#define STCG1(P, V) asm volatile("st.global.cg.u32 [%0], %1;" :: "l"(P), "r"(V))

#define LDFLAG(V, P) asm volatile("ld.relaxed.gpu.global.u32 %0, [%1];" : "=r"(V) : "l"(P) : "memory")
#define STFLAG(P, V) asm volatile("st.relaxed.gpu.global.u32 [%0], %1;" :: "l"(P), "r"(V) : "memory")
#define FENCE_GPU()  asm volatile("fence.acq_rel.gpu;" ::: "memory")

__device__ __forceinline__ void bar_pub(unsigned* flags, int bid, unsigned fl) {
    __syncthreads();
    if (threadIdx.x == 0) { FENCE_GPU(); STFLAG(flags + bid * FLSTR, fl); }
}
__device__ __forceinline__ void bar_poll(unsigned* flags, unsigned fl, int warp, int lane) {
    if (warp == 0) {
        bool ok;
        do {
            unsigned t0, t1, t2, t3;
            LDFLAG(t0, flags + lane * FLSTR);
            LDFLAG(t1, flags + (lane + 32) * FLSTR);
            LDFLAG(t2, flags + (lane + 64) * FLSTR);
            LDFLAG(t3, flags + (lane + 96) * FLSTR);
            ok = (t0 >= fl) & (t1 >= fl) & (t2 >= fl) & (t3 >= fl);
        } while (!__all_sync(0xffffffffu, ok));
        FENCE_GPU();
    }
    __syncthreads();
}

// ---- encoder MMA core: fragment-major A loads ----
template<int NKT>
__device__ __forceinline__ void enc_mma_run(
    float acc[4][4], const uint32_t* __restrict__ hb, const uint32_t* __restrict__ Wp,
    int ktbase, int wj, int lane, int qc, int qr)
{
    uint2 A[2][2][4];
#define ENC_LOAD(buf, c) { \
    _Pragma("unroll") \
    for (int u2 = 0; u2 < 2; ++u2) { \
        const uint32_t* ab = hb + (((wj * 32 + ktbase + (c) * 2 + u2) * 4) << 6) + lane * 2; \
        LDCG2(A[buf][u2][0], ab); \
        LDCG2(A[buf][u2][1], ab + 64); \
        LDCG2(A[buf][u2][2], ab + 128); \
        LDCG2(A[buf][u2][3], ab + 192); } }
    ENC_LOAD(0, 0)
    #pragma unroll
    for (int c = 0; c < NKT / 2; ++c) {
        if (c + 1 < NKT / 2) ENC_LOAD((c + 1) & 1, c + 1)
        #pragma unroll
        for (int u = 0; u < 2; ++u) {
            int po = (ktbase + c * 2 + u) * 16 + qc * 2;
            uint2 a0 = A[c & 1][u][0], a1 = A[c & 1][u][1];
            uint2 a2 = A[c & 1][u][2], a3 = A[c & 1][u][3];
            #pragma unroll
            for (int i = 0; i < 4; ++i) {
                const uint32_t* wr = Wp + (i * 8 + qr) * WPAD;
                uint2 b0 = *(const uint2*)(wr + po);
                uint2 b1 = *(const uint2*)(wr + po + 8);
                MMA_BF16(acc[i], a0.x, a1.x, a2.x, a3.x, b0.x, b1.x);
                MMA_BF16(acc[i], a0.x, a1.x, a2.x, a3.x, b0.y, b1.y);
                MMA_BF16(acc[i], a0.y, a1.y, a2.y, a3.y, b0.x, b1.x);
            }
        }
    }
#undef ENC_LOAD
}

// ---- decoder MMA core ----
template<int NKT>
__device__ __forceinline__ void dec_mma_run(
    float acc[4][4], const uint32_t* __restrict__ hb, const __nv_bfloat16* __restrict__ Wp,
    int ktbase, int wj, int lane, int qc, int qr)
{
    uint32_t A[2][2][4];
#define DEC_LOAD(buf, c) { \
    _Pragma("unroll") \
    for (int u2 = 0; u2 < 2; ++u2) { \
        const uint32_t* ab = hb + (((wj * 32 + ktbase + (c) * 2 + u2) * 4) << 5) + lane; \
        LDCG1(A[buf][u2][0], ab); \
        LDCG1(A[buf][u2][1], ab + 32); \
        LDCG1(A[buf][u2][2], ab + 64); \
        LDCG1(A[buf][u2][3], ab + 96); } }
    DEC_LOAD(0, 0)
    #pragma unroll
    for (int c = 0; c < NKT / 2; ++c) {
        if (c + 1 < NKT / 2) DEC_LOAD((c + 1) & 1, c + 1)
        #pragma unroll
        for (int u = 0; u < 2; ++u) {
            int k0 = (ktbase + c * 2 + u) * 16 + qc * 2;
            uint32_t a0 = A[c & 1][u][0], a1 = A[c & 1][u][1];
            uint32_t a2 = A[c & 1][u][2], a3 = A[c & 1][u][3];
            #pragma unroll
            for (int i = 0; i < 4; ++i) {
                const __nv_bfloat16* wr = Wp + (i * 8 + qr) * SPAD;
                uint32_t b0 = *(const uint32_t*)(wr + k0);
                uint32_t b1 = *(const uint32_t*)(wr + k0 + 8);
                MMA_BF16(acc[i], a0, a1, a2, a3, b0, b1);
            }
        }
    }
#undef DEC_LOAD
}

// ================= fused encoder scan =================
__global__ void __launch_bounds__(NSCAN, 1) enc_scan(
    const float* __restrict__ Whh0, const float* __restrict__ Wih1,
    const float* __restrict__ Whh1, const float* __restrict__ gx)
{
    extern __shared__ uint32_t smu[];
    float4* Sred = (float4*)(smu + 64 * WPAD);
    const int tid = threadIdx.x, bid = blockIdx.x;
    const int layerid = bid >> 6, ci = bid & 63, j0 = ci * 8;
    const int warp = tid >> 5, lane = tid & 31;
    const int grp = warp >> 2, wj = warp & 3;
    const int qr = lane >> 2, qc = lane & 3;
    const int r0 = wj * 16 + qr;
    const int wroff = (((wj * 32 + (ci >> 1)) * 4 + (ci & 1) * 2) << 6) + lane * 2;

    if (layerid == 0) {
        for (int idx = tid; idx < 32 * 256; idx += NSCAN) {
            int rl = idx >> 8, p = idx & 255;
            int grow = (rl >> 3) * 512 + j0 + (rl & 7);
            float2 v = *(const float2*)(Whh0 + (size_t)grow * 512 + 2 * p);
            __nv_bfloat16 h0 = __float2bfloat16_rn(v.x), h1v = __float2bfloat16_rn(v.y);
            __nv_bfloat16 l0 = __float2bfloat16_rn(v.x - __bfloat162float(h0));
            __nv_bfloat16 l1 = __float2bfloat16_rn(v.y - __bfloat162float(h1v));
            smu[rl * WPAD + 2 * p]     = pk2(h0, h1v);
            smu[rl * WPAD + 2 * p + 1] = pk2(l0, l1);
        }
        for (int idx = tid; idx < 512; idx += NSCAN)
            STCG1(&g_e0[1][ci * 512 + idx], 0u);
    } else {
        for (int idx = tid; idx < 2 * 32 * 256; idx += NSCAN) {
            int w = idx >= 32 * 256;
            int ii = idx - w * 32 * 256;
            int rl = ii >> 8, p = ii & 255;
            int grow = (rl >> 3) * 512 + j0 + (rl & 7);
            const float* W = w ? Whh1 : Wih1;
            float2 v = *(const float2*)(W + (size_t)grow * 512 + 2 * p);
            __nv_bfloat16 h0 = __float2bfloat16_rn(v.x), h1v = __float2bfloat16_rn(v.y);
            __nv_bfloat16 l0 = __float2bfloat16_rn(v.x - __bfloat162float(h0));
            __nv_bfloat16 l1 = __float2bfloat16_rn(v.y - __bfloat162float(h1v));
            uint32_t* dst = smu + w * 32 * WPAD + rl * WPAD;
            dst[2 * p]     = pk2(h0, h1v);
            dst[2 * p + 1] = pk2(l0, l1);
        }
        for (int idx = tid; idx < 512; idx += NSCAN)
            STCG1(&g_e1[1][ci * 512 + idx], 0u);
    }

    float pf[4][4];
    if (layerid == 1 && grp == 0) {
        #pragma unroll
        for (int i = 0; i < 4; ++i) {
            int col = i * 512 + j0 + qc * 2;
            float b0 = g_bsum[1][col], b1 = g_bsum[1][col + 1];
            pf[i][0] = b0; pf[i][1] = b1; pf[i][2] = b0; pf[i][3] = b1;
        }
    }
    unsigned fl = 1;
    bar_pub(g_flagsE, bid, fl);
    if (layerid == 0 && grp == 0) {
        #pragma unroll
        for (int i = 0; i < 4; ++i) {
            int col = i * 512 + j0 + qc * 2;
            float2 lo = *(const float2*)(gx + (size_t)r0       * 2048 + col);
            float2 hi = *(const float2*)(gx + (size_t)(r0 + 8) * 2048 + col);
            pf[i][0] = lo.x; pf[i][1] = lo.y; pf[i][2] = hi.x; pf[i][3] = hi.y;
        }
    }
    bar_poll(g_flagsE, fl, warp, lane); fl++;

    float creg[4] = {0.f, 0.f, 0.f, 0.f};
    for (int r = 0; r <= TT; ++r) {
        const bool active = (layerid == 0) ? (r < TT) : (r >= 1);
        float acc[4][4];
        float4* Sb = Sred + (r & 1) * (3 * 512);
        if (active) {
            #pragma unroll
            for (int i = 0; i < 4; ++i)
                #pragma unroll
                for (int k = 0; k < 4; ++k) acc[i][k] = (grp == 0) ? pf[i][k] : 0.f;

            if (layerid == 0) {
                enc_mma_run<8>(acc, g_e0[(r - 1) & 1], smu, grp * 8, wj, lane, qc, qr);
            } else {
                const uint32_t* hb = (grp < 2) ? g_e1[r & 1] : g_e0[(r - 1) & 1];
                const uint32_t* Wp = (grp < 2) ? (smu + 32 * WPAD) : smu;
                enc_mma_run<16>(acc, hb, Wp, (grp & 1) * 16, wj, lane, qc, qr);
            }
            if (grp > 0) {
                int base = (grp - 1) * 512 + (wj * 32 + lane) * 4;
                #pragma unroll
                for (int i = 0; i < 4; ++i)
                    Sb[base + i] = make_float4(acc[i][0], acc[i][1], acc[i][2], acc[i][3]);
            }
        }
        __syncthreads();
        if (active && grp == 0) {
            int base = (wj * 32 + lane) * 4;
            #pragma unroll
            for (int s = 0; s < 3; ++s)
                #pragma unroll
                for (int i = 0; i < 4; ++i) {
                    float4 p = Sb[s * 512 + base + i];
                    acc[i][0] += p.x; acc[i][1] += p.y; acc[i][2] += p.z; acc[i][3] += p.w;
                }
            float hv[4];
            #pragma unroll
            for (int k = 0; k < 4; ++k) {
                float ig = fsig(acc[0][k]);
                float fg = fsig(acc[1][k]);
                float gg = ftanhx(acc[2][k]);
                float og = fsig(acc[3][k]);
                creg[k] = fg * creg[k] + ig * gg;
                hv[k]   = og * ftanhx(creg[k]);
            }
            __nv_bfloat16 hh[4], hl[4];
            #pragma unroll
            for (int k = 0; k < 4; ++k) {
                hh[k] = __float2bfloat16_rn(hv[k]);
                hl[k] = __float2bfloat16_rn(hv[k] - __bfloat162float(hh[k]));
            }
            uint32_t* wb = (layerid == 0) ? g_e0[r & 1] : g_e1[(r - 1) & 1];
            STCG2(wb + wroff,      pk2(hh[0], hh[1]), pk2(hl[0], hl[1]));
            STCG2(wb + wroff + 64, pk2(hh[2], hh[3]), pk2(hl[2], hl[3]));
        }
        if (r < TT) {
            bar_pub(g_flagsE, bid, fl);
            if (layerid == 0 && grp == 0 && r + 1 < TT) {
                #pragma unroll
                for (int i = 0; i < 4; ++i) {
                    int col = i * 512 + j0 + qc * 2;
                    float2 lo = *(const float2*)(gx + (size_t)((r + 1) * 64 + r0)     * 2048 + col);
                    float2 hi = *(const float2*)(gx + (size_t)((r + 1) * 64 + r0 + 8) * 2048 + col);
                    pf[i][0] = lo.x; pf[i][1] = lo.y; pf[i][2] = hi.x; pf[i][3] = hi.y;
                }
            }
            bar_poll(g_flagsE, fl, warp, lane); fl++;
        }
    }
}

// ================= fused decoder scan =================
__global__ void __launch_bounds__(NSCAN, 1) dec_scan(
    const float* __restrict__ Whh0, const float* __restrict__ Wih1,
    const float* __restrict__ Whh1)
{
    extern __shared__ uint32_t smu[];
    __nv_bfloat16* Wsm = (__nv_bfloat16*)smu;
    float4* Sred = (float4*)(smu + 64 * (SPAD / 2));
    const int tid = threadIdx.x, bid = blockIdx.x;
    const int layerid = bid >> 6, ci = bid & 63, j0 = ci * 8;
    const int warp = tid >> 5, lane = tid & 31;
    const int grp = warp >> 2, wj = warp & 3;
    const int qr = lane >> 2, qc = lane & 3;
    const int r0 = wj * 16 + qr;
    const int wroff = (((wj * 32 + (ci >> 1)) * 4 + (ci & 1) * 2) << 5) + lane;

    if (layerid == 0) {
        for (int idx = tid; idx < 32 * 256; idx += NSCAN) {
            int rl = idx >> 8, p = idx & 255;
            int grow = (rl >> 3) * 512 + j0 + (rl & 7);
            float2 v = *(const float2*)(Whh0 + (size_t)grow * 512 + 2 * p);
            ((uint32_t*)Wsm)[rl * (SPAD / 2) + p] =
                pk2(__float2bfloat16(v.x), __float2bfloat16(v.y));
        }
        for (int idx = tid; idx < 64 * 4; idx += NSCAN) {
            int row = idx >> 2, pp = idx & 3;
            float2 v = *(const float2*)(g_M + row * 512 + j0 + 2 * pp);
            STCG1(&g_d0[1][fidx_dec(row, 4 * ci + pp)],
                  pk2(__float2bfloat16(v.x), __float2bfloat16(v.y)));
        }
    } else {
        for (int idx = tid; idx < 2 * 32 * 256; idx += NSCAN) {
            int w = idx >= 32 * 256;
            int ii = idx - w * 32 * 256;
            int rl = ii >> 8, p = ii & 255;
            int grow = (rl >> 3) * 512 + j0 + (rl & 7);
            const float* W = w ? Wih1 : Whh1;
            float2 v = *(const float2*)(W + (size_t)grow * 512 + 2 * p);
            ((uint32_t*)Wsm)[w * 32 * (SPAD / 2) + rl * (SPAD / 2) + p] =
                pk2(__float2bfloat16(v.x), __float2bfloat16(v.y));
        }
        for (int idx = tid; idx < 64 * 4; idx += NSCAN) {
            int row = idx >> 2, pp = idx & 3;
            float2 v = *(const float2*)(g_M + 32768 + row * 512 + j0 + 2 * pp);
            STCG1(&g_d1[1][fidx_dec(row, 4 * ci + pp)],
                  pk2(__float2bfloat16(v.x), __float2bfloat16(v.y)));
        }
    }

    float pf[4][4];
    if (grp == 0) {
        const float* bs = g_bsum[layerid == 0 ? 2 : 3];
        #pragma unroll
        for (int i = 0; i < 4; ++i) {
            int col = i * 512 + j0 + qc * 2;
            float b0 = bs[col], b1 = bs[col + 1];
            pf[i][0] = b0; pf[i][1] = b1; pf[i][2] = b0; pf[i][3] = b1;
        }
    }
    unsigned fl = 1;
    bar_pub(g_flagsD, bid, fl);
    bar_poll(g_flagsD, fl, warp, lane); fl++;

    float creg[4] = {0.f, 0.f, 0.f, 0.f};
    for (int r = 0; r <= TT; ++r) {
        const bool active = (layerid == 0) ? (r < TT) : (r >= 1);
        float acc[4][4];
        uint32_t q0 = 0, q1 = 0;
        float4* Sb = Sred + (r & 1) * (3 * 512);
        if (active) {
            #pragma unroll
            for (int i = 0; i < 4; ++i)
                #pragma unroll
                for (int k = 0; k < 4; ++k) acc[i][k] = (grp == 0) ? pf[i][k] : 0.f;

            if (layerid == 0) {
                dec_mma_run<8>(acc, g_d0[(r - 1) & 1], Wsm, grp * 8, wj, lane, qc, qr);
            } else {
                const uint32_t* hb = (grp < 2) ? g_d1[r & 1] : g_d0[(r - 1) & 1];
                const __nv_bfloat16* Wp = (grp < 2) ? Wsm : Wsm + 32 * SPAD;
                dec_mma_run<16>(acc, hb, Wp, (grp & 1) * 16, wj, lane, qc, qr);
            }
            if (grp > 0) {
                int base = (grp - 1) * 512 + (wj * 32 + lane) * 4;
                #pragma unroll
                for (int i = 0; i < 4; ++i)
                    Sb[base + i] = make_float4(acc[i][0], acc[i][1], acc[i][2], acc[i][3]);
            }
        }
        __syncthreads();
        if (active && grp == 0) {
            int base = (wj * 32 + lane) * 4;
            #pragma unroll
            for (int s = 0; s < 3; ++s)
                #pragma unroll
                for (int i = 0; i < 4; ++i) {
                    float4 p = Sb[s * 512 + base + i];
                    acc[i][0] += p.x; acc[i][1] += p.y; acc[i][2] += p.z; acc[i][3] += p.w;
                }
            float hv[4];
            #pragma unroll
            for (int k = 0; k < 4; ++k) {
                float ig = fsig(acc[0][k]);
                float fg = fsig(acc[1][k]);
                float gg = ftanhx(acc[2][k]);
                float og = fsig(acc[3][k]);
                creg[k] = fg * creg[k] + ig * gg;
                hv[k]   = og * ftanhx(creg[k]);
            }
            q0 = pk2(__float2bfloat16_rn(hv[0]), __float2bfloat16_rn(hv[1]));
            q1 = pk2(__float2bfloat16_rn(hv[2]), __float2bfloat16_rn(hv[3]));
            uint32_t* wb = (layerid == 0) ? g_d0[r & 1] : g_d1[(r - 1) & 1];
            STCG1(wb + wroff, q0);
            STCG1(wb + wroff + 32, q1);
        }
        if (r < TT) {
            bar_pub(g_flagsD, bid, fl);
            if (layerid == 1 && grp == 0 && r >= 1) {
                int t = r - 1, cb = j0 + qc * 2;
                *(uint32_t*)(g_hs + (size_t)(t * 64 + r0)     * 512 + cb) = q0;
                *(uint32_t*)(g_hs + (size_t)(t * 64 + r0 + 8) * 512 + cb) = q1;
            }
            bar_poll(g_flagsD, fl, warp, lane); fl++;
        } else if (layerid == 1 && grp == 0) {
            int t = TT - 1, cb = j0 + qc * 2;
            *(uint32_t*)(g_hs + (size_t)(t * 64 + r0)     * 512 + cb) = q0;
            *(uint32_t*)(g_hs + (size_t)(t * 64 + r0 + 8) * 512 + cb) = q1;
        }
    }
}

// ================= split-bf16 GEMM 128x128 =================
__global__ void __launch_bounds__(256, 2) gemm_split_kernel(
    const __nv_bfloat16* __restrict__ Ah, const __nv_bfloat16* __restrict__ Al,
    const __nv_bfloat16* __restrict__ Bh, const __nv_bfloat16* __restrict__ Bl,
    const float* __restrict__ bias, float* __restrict__ Cout, int N, int K)
{
    __shared__ __nv_bfloat16 Ash[128 * 40];
    __shared__ __nv_bfloat16 Asl[128 * 40];
    __shared__ __nv_bfloat16 Bsh[128 * 40];
    __shared__ __nv_bfloat16 Bsl[128 * 40];
    const int tid  = threadIdx.x;
    const int warp = tid >> 5, lane = tid & 31;
    const int qr   = lane >> 2, qc = lane & 3;
    const int wm   = warp >> 2, wn = warp & 3;
    const int m0   = blockIdx.x * 128;
    const int n0   = blockIdx.y * 128;

    float acc[4][4][4];
    #pragma unroll
    for (int a = 0; a < 4; ++a)
        #pragma unroll
        for (int b = 0; b < 4; ++b)
            #pragma unroll
            for (int c = 0; c < 4; ++c) acc[a][b][c] = 0.f;

    for (int kt = 0; kt < K; kt += 32) {
        #pragma unroll
        for (int u = 0; u < 2; ++u) {
            int idx = tid + u * 256;
            int r = idx >> 2, c8 = (idx & 3) << 3;
            *(uint4*)(Ash + r * 40 + c8) = *(const uint4*)(Ah + (size_t)(m0 + r) * K + kt + c8);
            *(uint4*)(Asl + r * 40 + c8) = *(const uint4*)(Al + (size_t)(m0 + r) * K + kt + c8);
            *(uint4*)(Bsh + r * 40 + c8) = *(const uint4*)(Bh + (size_t)(n0 + r) * K + kt + c8);
            *(uint4*)(Bsl + r * 40 + c8) = *(const uint4*)(Bl + (size_t)(n0 + r) * K + kt + c8);
        }
        __syncthreads();
        #pragma unroll
        for (int kk = 0; kk < 2; ++kk) {
            const int k0 = kk * 16 + qc * 2;
            #pragma unroll
            for (int mi = 0; mi < 4; ++mi) {
                int ar = wm * 64 + mi * 16 + qr;
                uint32_t ah0 = *(const uint32_t*)(Ash + ar * 40 + k0);
                uint32_t ah1 = *(const uint32_t*)(Ash + (ar + 8) * 40 + k0);
                uint32_t ah2 = *(const uint32_t*)(Ash + ar * 40 + k0 + 8);
                uint32_t ah3 = *(const uint32_t*)(Ash + (ar + 8) * 40 + k0 + 8);
                uint32_t al0 = *(const uint32_t*)(Asl + ar * 40 + k0);
                uint32_t al1 = *(const uint32_t*)(Asl + (ar + 8) * 40 + k0);
                uint32_t al2 = *(const uint32_t*)(Asl + ar * 40 + k0 + 8);
                uint32_t al3 = *(const uint32_t*)(Asl + (ar + 8) * 40 + k0 + 8);
                #pragma unroll
                for (int ni = 0; ni < 4; ++ni) {
                    int br = wn * 32 + ni * 8 + qr;
                    uint32_t bh0 = *(const uint32_t*)(Bsh + br * 40 + k0);
                    uint32_t bh1 = *(const uint32_t*)(Bsh + br * 40 + k0 + 8);
                    uint32_t bl0 = *(const uint32_t*)(Bsl + br * 40 + k0);
                    uint32_t bl1 = *(const uint32_t*)(Bsl + br * 40 + k0 + 8);
                    MMA_BF16(acc[mi][ni], ah0, ah1, ah2, ah3, bh0, bh1);
                    MMA_BF16(acc[mi][ni], ah0, ah1, ah2, ah3, bl0, bl1);
                    MMA_BF16(acc[mi][ni], al0, al1, al2, al3, bh0, bh1);
                }
            }
        }
        __syncthreads();
    }
    #pragma unroll
    for (int mi = 0; mi < 4; ++mi)
        #pragma unroll
        for (int ni = 0; ni < 4; ++ni) {
            int gn = n0 + wn * 32 + ni * 8 + qc * 2;
            float bv0 = bias[gn], bv1 = bias[gn + 1];
            #pragma unroll
            for (int h = 0; h < 2; ++h) {
                int gm = m0 + wm * 64 + mi * 16 + qr + h * 8;
                *(float2*)(Cout + (size_t)gm * N + gn) =
                    make_float2(acc[mi][ni][h * 2 + 0] + bv0, acc[mi][ni][h * 2 + 1] + bv1);
            }
        }
}

// ================= plain bf16 GEMM (output projection) =================
__global__ void __launch_bounds__(256, 2) gemm_bf16_kernel(
    const __nv_bfloat16* __restrict__ A, const __nv_bfloat16* __restrict__ Bw,
    const float* __restrict__ bias, float* __restrict__ Cout, int N, int K, int mode)
{
    __shared__ __nv_bfloat16 As[128 * 40];
    __shared__ __nv_bfloat16 Bs[128 * 40];
    const int tid  = threadIdx.x;
    const int warp = tid >> 5, lane = tid & 31;
    const int qr   = lane >> 2, qc = lane & 3;
    const int wm   = warp >> 2, wn = warp & 3;
    const int m0   = blockIdx.x * 128;
    const int n0   = blockIdx.y * 128;

    float acc[4][4][4];
    #pragma unroll
    for (int a = 0; a < 4; ++a)
        #pragma unroll
        for (int b = 0; b < 4; ++b)
            #pragma unroll
            for (int c = 0; c < 4; ++c) acc[a][b][c] = 0.f;

    for (int kt = 0; kt < K; kt += 32) {
        #pragma unroll
        for (int u = 0; u < 2; ++u) {
            int idx = tid + u * 256;
            int r = idx >> 2, c8 = (idx & 3) << 3;
            *(uint4*)(As + r * 40 + c8) = *(const uint4*)(A + (size_t)(m0 + r) * K + kt + c8);
            *(uint4*)(Bs + r * 40 + c8) = *(const uint4*)(Bw + (size_t)(n0 + r) * K + kt + c8);
        }
        __syncthreads();
        #pragma unroll
        for (int kk = 0; kk < 2; ++kk) {
            const int k0 = kk * 16 + qc * 2;
            #pragma unroll
            for (int mi = 0; mi < 4; ++mi) {
                int ar = wm * 64 + mi * 16 + qr;
                uint32_t a0 = *(const uint32_t*)(As + ar * 40 + k0);
                uint32_t a1 = *(const uint32_t*)(As + (ar + 8) * 40 + k0);
                uint32_t a2 = *(const uint32_t*)(As + ar * 40 + k0 + 8);
                uint32_t a3 = *(const uint32_t*)(As + (ar + 8) * 40 + k0 + 8);
                #pragma unroll
                for (int ni = 0; ni < 4; ++ni) {
                    int br = wn * 32 + ni * 8 + qr;
                    uint32_t b0 = *(const uint32_t*)(Bs + br * 40 + k0);
                    uint32_t b1 = *(const uint32_t*)(Bs + br * 40 + k0 + 8);
                    MMA_BF16(acc[mi][ni], a0, a1, a2, a3, b0, b1);
                }
            }
        }
        __syncthreads();
    }
    #pragma unroll
    for (int mi = 0; mi < 4; ++mi)
        #pragma unroll
        for (int ni = 0; ni < 4; ++ni) {
            int gn = n0 + wn * 32 + ni * 8 + qc * 2;
            float bv0 = bias[gn], bv1 = bias[gn + 1];
            #pragma unroll
            for (int h = 0; h < 2; ++h) {
                int gm = m0 + wm * 64 + mi * 16 + qr + h * 8;
                float v0 = acc[mi][ni][h * 2 + 0] + bv0;
                float v1 = acc[mi][ni][h * 2 + 1] + bv1;
                if (mode == 1) {
                    int tt = gm >> 6, bb = gm & 63;
                    *(float2*)(Cout + ((size_t)bb * TT + tt) * DD + gn) =
                        make_float2(fsig(v0), fsig(v1));
                } else {
                    *(float2*)(Cout + (size_t)gm * N + gn) = make_float2(v0, v1);
                }
            }
        }
}

// ================= prep / latent kernels =================
__global__ void prep_bias_kernel(
    const float* __restrict__ b0a, const float* __restrict__ b0b,
    const float* __restrict__ b1a, const float* __restrict__ b1b,
    const float* __restrict__ b2a, const float* __restrict__ b2b,
    const float* __restrict__ b3a, const float* __restrict__ b3b)
{
    int i = blockIdx.x * blockDim.x + threadIdx.x;
    if (i < 4 * G4) {
        int l = i >> 11, j = i & (G4 - 1);
        const float* pa = (l == 0) ? b0a : (l == 1) ? b1a : (l == 2) ? b2a : b3a;
        const float* pb = (l == 0) ? b0b : (l == 1) ? b1b : (l == 2) ? b2b : b3b;
        g_bsum[l][j] = pa[j] + pb[j];
    }
    if (i < NCTA) g_flagsE[i * FLSTR] = 0u;
}
__global__ void prep_xw_kernel(const float* __restrict__ x, const float* __restrict__ W) {
    int i = blockIdx.x * blockDim.x + threadIdx.x;
    if (i < TB * DD) {
        int d = i & (DD - 1);
        int r = i >> 7;
        int b = r & 63, t = r >> 6;
        float v = x[((size_t)b * TT + t) * DD + d];
        __nv_bfloat16 h = __float2bfloat16_rn(v);
        g_xth[i] = h;
        g_xtl[i] = __float2bfloat16_rn(v - __bfloat162float(h));
    }
    if (i < G4 * DD) {
        float v = W[i];
        __nv_bfloat16 h = __float2bfloat16_rn(v);
        g_wih0h[i] = h;
        g_wih0l[i] = __float2bfloat16_rn(v - __bfloat162float(h));
    }
}
__global__ void prep_opw_kernel(const float* __restrict__ W) {
    int i = blockIdx.x * blockDim.x + threadIdx.x;
    if (i < DD * HH) g_opw[i] = __float2bfloat16(W[i]);
}
__global__ void z_kernel(const float* __restrict__ tlW, const float* __restrict__ tlb,
                         float* __restrict__ zout) {
    int idx = blockIdx.x * blockDim.x + threadIdx.x;
    if (idx < BB * ZZ) {
        int b = idx >> 6, j = idx & 63;
        float s = 0.f;
        for (int p = 0; p < 256; ++p) {
            int off = fidx_enc(b, p);
            uint32_t wh = g_e1[1][off], wl = g_e1[1][off + 1];
            float h0 = bfl(wh, 0) + bfl(wl, 0);
            float h1 = bfl(wh, 1) + bfl(wl, 1);
            s += h0 * tlW[j * 512 + 2 * p] + h1 * tlW[j * 512 + 2 * p + 1];
        }
        s += tlb[j];
        g_zbuf[idx] = s;
        zout[idx] = s;
    }
}
__global__ void m_kernel(const float* __restrict__ lhW, const float* __restrict__ lhb) {
    int b = blockIdx.x, k1 = threadIdx.x;
    float s = 0.f;
    for (int j = 0; j < 64; ++j)
        s += g_zbuf[b * 64 + j] * lhW[k1 * 64 + j];
    g_M[b * 1024 + k1] = tanhf(s + lhb[k1]);
    if (b == 0 && k1 < NCTA) g_flagsD[k1 * FLSTR] = 0u;
}

extern "C" void kernel_launch(void* const* d_in, const int* in_sizes, int n_in,
                              void* d_out, int out_size) {
    const float* x     = (const float*)d_in[0];
    const float* eWih0 = (const float*)d_in[1];
    const float* eWhh0 = (const float*)d_in[2];
    const float* ebih0 = (const float*)d_in[3];
    const float* ebhh0 = (const float*)d_in[4];
    const float* eWih1 = (const float*)d_in[5];
    const float* eWhh1 = (const float*)d_in[6];
    const float* ebih1 = (const float*)d_in[7];
    const float* ebhh1 = (const float*)d_in[8];
    const float* dWhh0 = (const float*)d_in[10];
    const float* dbih0 = (const float*)d_in[11];
    const float* dbhh0 = (const float*)d_in[12];
    const float* dWih1 = (const float*)d_in[13];
    const float* dWhh1 = (const float*)d_in[14];
    const float* dbih1 = (const float*)d_in[15];
    const float* dbhh1 = (const float*)d_in[16];
    const float* tlW   = (const float*)d_in[17];
    const float* tlb   = (const float*)d_in[18];
    const float* lhW   = (const float*)d_in[19];
    const float* lhb   = (const float*)d_in[20];
    const float* opW   = (const float*)d_in[21];
    const float* opb   = (const float*)d_in[22];
    float* out = (float*)d_out;

    __nv_bfloat16 *p_xth, *p_xtl, *p_w0h, *p_w0l, *p_opw, *p_hs;
    float *p_gx, *p_bs;
    cudaGetSymbolAddress((void**)&p_xth, g_xth);
    cudaGetSymbolAddress((void**)&p_xtl, g_xtl);
    cudaGetSymbolAddress((void**)&p_gx, g_gx);
    cudaGetSymbolAddress((void**)&p_hs, g_hs);
    cudaGetSymbolAddress((void**)&p_bs, g_bsum);
    cudaGetSymbolAddress((void**)&p_w0h, g_wih0h);
    cudaGetSymbolAddress((void**)&p_w0l, g_wih0l);
    cudaGetSymbolAddress((void**)&p_opw, g_opw);

    const int ENC_SMEM = 64 * WPAD * 4 + 2 * 3 * 512 * 16;
    const int DEC_SMEM = 64 * (SPAD / 2) * 4 + 2 * 3 * 512 * 16;
    cudaFuncSetAttribute(enc_scan, cudaFuncAttributeMaxDynamicSharedMemorySize, ENC_SMEM);
    cudaFuncSetAttribute(dec_scan, cudaFuncAttributeMaxDynamicSharedMemorySize, DEC_SMEM);

    prep_bias_kernel<<<32, 256>>>(ebih0, ebhh0, ebih1, ebhh1, dbih0, dbhh0, dbih1, dbhh1);
    prep_xw_kernel<<<TB * DD / 256, 256>>>(x, eWih0);
    dim3 gemm_grid(TB / 128, G4 / 128);
    gemm_split_kernel<<<gemm_grid, 256>>>(p_xth, p_xtl, p_w0h, p_w0l, p_bs + 0 * G4, p_gx, G4, DD);
    enc_scan<<<NCTA, NSCAN, ENC_SMEM>>>(eWhh0, eWih1, eWhh1, p_gx);
    z_kernel<<<(BB * ZZ + 255) / 256, 256>>>(tlW, tlb, out + (size_t)BB * TT * DD);
    m_kernel<<<BB, 1024>>>(lhW, lhb);
    dec_scan<<<NCTA, NSCAN, DEC_SMEM>>>(dWhh0, dWih1, dWhh1);
    prep_opw_kernel<<<DD * HH / 256, 256>>>(opW);
    dim3 op_grid(TB / 128, 1);
    gemm_bf16_kernel<<<op_grid, 256>>>(p_hs, p_opw, opb, out, DD, HH, 1);
}